// round 3
// baseline (speedup 1.0000x reference)
#include <cuda_runtime.h>
#include <cuda_bf16.h>
#include <cstdint>

// Problem constants
constexpr int BATCH   = 4;
constexpr int GXD     = 480;
constexpr int GYD     = 360;
constexpr int CIN     = 64;
constexpr int COUT    = 32;
constexpr int NPTS    = 480000;
constexpr int SEG_PER_B = GXD * GYD;          // 172800
constexpr int NSEG    = BATCH * SEG_PER_B;    // 691200

// Scratch: pooled max per (voxel, channel) as order-preserving-encoded uint32,
// init value 0 == "-infinity" (no real float encodes to 0).
__device__ __align__(16) unsigned int g_pooled[(size_t)NSEG * CIN];
__device__ __align__(16) int          g_occ[NSEG];

__device__ __forceinline__ unsigned int enc_f(float f) {
    unsigned int u = __float_as_uint(f);
    return (u & 0x80000000u) ? ~u : (u | 0x80000000u);
}
__device__ __forceinline__ float dec_f(unsigned int u) {
    return __uint_as_float((u & 0x80000000u) ? (u & 0x7FFFFFFFu) : ~u);
}

// ---------------------------------------------------------------------------
// Kernel 1: zero the scratch (encoded 0 == -inf, occ = 0)
// ---------------------------------------------------------------------------
__global__ void init_kernel() {
    const unsigned int n4 = (unsigned int)((size_t)NSEG * CIN / 4); // 11,059,200
    unsigned int i = blockIdx.x * blockDim.x + threadIdx.x;
    uint4 z = make_uint4(0u, 0u, 0u, 0u);
    if (i < n4) reinterpret_cast<uint4*>(g_pooled)[i] = z;
    if (i < (unsigned int)(NSEG / 4)) reinterpret_cast<uint4*>(g_occ)[i] = z;
}

// ---------------------------------------------------------------------------
// Kernel 2: scatter-max. One thread per (point, channel).
// Within a warp, p is uniform (64 channels = 2 warps per point), so the
// index loads broadcast from L1 and seg is computed once per warp.
// ---------------------------------------------------------------------------
__global__ void scatter_kernel(const float* __restrict__ fea,
                               const int*   __restrict__ ind,
                               const int*   __restrict__ bidx) {
    int i = blockIdx.x * blockDim.x + threadIdx.x;
    if (i >= NPTS * CIN) return;
    int p = i >> 6;
    int c = i & 63;
    int seg = bidx[p] * SEG_PER_B + ind[2 * p] * GYD + ind[2 * p + 1];
    unsigned int u = enc_f(fea[i]);
    atomicMax(&g_pooled[(size_t)seg * CIN + c], u);  // return unused -> REDG
    if (c == 0) g_occ[seg] = 1;
}

// ---------------------------------------------------------------------------
// Kernel 3: per-voxel Linear(64->32)+ReLU, transposed coalesced write.
// One block = 64 consecutive voxels (64 divides SEG_PER_B, so no batch
// boundary crossing). 256 threads = 8 warps; each warp owns 8 voxels, each
// lane owns one output channel with its W column held in registers. Pool
// reads are warp-uniform broadcast LDS.128 (conflict-free). Output is staged
// in a [32][65] padded shared tile, then written with 128B-coalesced stores.
// ---------------------------------------------------------------------------
__global__ void __launch_bounds__(256, 2)
compress_kernel(const float* __restrict__ W,
                const float* __restrict__ bias,
                float* __restrict__ out) {
    __shared__ float sh_pool[64 * 64];   // [local_seg][c]
    __shared__ float sh_out[COUT * 65];  // [co][seg] padded
    __shared__ int   sh_occ[64];

    const int tid  = threadIdx.x;
    const int lane = tid & 31;
    const int wid  = tid >> 5;
    const int s0   = blockIdx.x * 64;

    if (tid < 64) sh_occ[tid] = g_occ[s0 + tid];

    // Each lane caches its output-channel column of W (64 floats) + bias.
    float wcol[64];
#pragma unroll
    for (int c = 0; c < 64; c++) wcol[c] = W[c * COUT + lane];
    const float bval = bias[lane];

    __syncthreads();

    // Cooperative decode-copy of occupied voxels into shared (linear layout,
    // conflict-free STS). Skip empty voxels entirely.
    const uint4* gp4 = reinterpret_cast<const uint4*>(g_pooled) + (size_t)s0 * 16;
#pragma unroll
    for (int it = 0; it < 4; it++) {
        int idx = tid + it * 256;           // 0..1023 uint4s = 64 segs * 16
        int ls  = idx >> 4;
        if (sh_occ[ls]) {
            uint4 u = gp4[idx];
            float4 f;
            f.x = dec_f(u.x); f.y = dec_f(u.y);
            f.z = dec_f(u.z); f.w = dec_f(u.w);
            *reinterpret_cast<float4*>(&sh_pool[idx * 4]) = f;
        }
    }
    __syncthreads();

    // GEMV: warp `wid` handles voxels wid*8 .. wid*8+7 (warp-uniform seg ->
    // broadcast LDS), lane handles output channel `lane`.
#pragma unroll
    for (int j = 0; j < 8; j++) {
        int s = wid * 8 + j;
        float r = 0.0f;
        if (sh_occ[s]) {
            float acc = bval;
            const float* pr = &sh_pool[s * 64];
#pragma unroll
            for (int cs = 0; cs < 64; cs += 4) {
                float4 p = *reinterpret_cast<const float4*>(&pr[cs]);
                acc = fmaf(p.x, wcol[cs + 0], acc);
                acc = fmaf(p.y, wcol[cs + 1], acc);
                acc = fmaf(p.z, wcol[cs + 2], acc);
                acc = fmaf(p.w, wcol[cs + 3], acc);
            }
            r = fmaxf(acc, 0.0f);
        }
        sh_out[lane * 65 + s] = r;   // stride-65: conflict-free
    }
    __syncthreads();

    // Coalesced transposed write: out[(bb*COUT+co)*SEG_PER_B + rem0 + y]
    const int bb   = s0 / SEG_PER_B;
    const int rem0 = s0 - bb * SEG_PER_B;
    float* ob = out + (size_t)bb * COUT * SEG_PER_B + rem0;
#pragma unroll
    for (int it = 0; it < 8; it++) {
        int idx = tid + it * 256;           // 0..2047
        int co = idx >> 6;
        int yy = idx & 63;
        ob[(size_t)co * SEG_PER_B + yy] = sh_out[co * 65 + yy];
    }
}

// ---------------------------------------------------------------------------
extern "C" void kernel_launch(void* const* d_in, const int* in_sizes, int n_in,
                              void* d_out, int out_size) {
    const float* pt_fea    = (const float*)d_in[0];
    const int*   pt_ind    = (const int*)d_in[1];
    const int*   batch_idx = (const int*)d_in[2];
    const float* W_comp    = (const float*)d_in[3];
    const float* b_comp    = (const float*)d_in[4];
    float* out = (float*)d_out;

    // 1) init scratch
    {
        const unsigned int n4 = (unsigned int)((size_t)NSEG * CIN / 4);
        int blocks = (int)((n4 + 255) / 256);
        init_kernel<<<blocks, 256>>>();
    }
    // 2) scatter-max
    {
        int total = NPTS * CIN;
        int blocks = (total + 255) / 256;
        scatter_kernel<<<blocks, 256>>>(pt_fea, pt_ind, batch_idx);
    }
    // 3) compress + transposed write
    {
        int blocks = NSEG / 64;  // 10800
        compress_kernel<<<blocks, 256>>>(W_comp, b_comp, out);
    }
}

// round 9
// speedup vs baseline: 1.4132x; 1.4132x over previous
#include <cuda_runtime.h>
#include <cuda_bf16.h>
#include <cstdint>
#include <cfloat>

// Problem constants
constexpr int BATCH     = 4;
constexpr int GXD       = 480;
constexpr int GYD       = 360;
constexpr int CIN       = 64;
constexpr int COUT      = 32;
constexpr int NPTS      = 480000;
constexpr int SEG_PER_B = GXD * GYD;          // 172800
constexpr int NSEG      = BATCH * SEG_PER_B;  // 691200
constexpr int SCAN_BLOCKS = NSEG / 1024;      // 675 (exact)

// Scratch (all fully rewritten every call -> graph-replay safe, ~9.4 MB total)
__device__ __align__(16) unsigned int g_counts[NSEG];   // per-voxel point count
__device__ __align__(16) unsigned int g_offs[NSEG];     // local excl scan, then cursor
__device__ unsigned int g_bsum[SCAN_BLOCKS];
__device__ unsigned int g_bsum_sc[SCAN_BLOCKS];
__device__ __align__(16) int          g_seg[NPTS];      // voxel id per point
__device__ __align__(16) unsigned int g_order[NPTS];    // point ids sorted by voxel

__device__ __forceinline__ unsigned int warp_incl_scan(unsigned int v) {
#pragma unroll
    for (int d = 1; d < 32; d <<= 1) {
        unsigned int n = __shfl_up_sync(0xffffffffu, v, d);
        if ((threadIdx.x & 31) >= d) v += n;
    }
    return v;
}

// ---------------------------------------------------------------------------
// K1a: zero the per-voxel counters (2.76 MB, trivially fast)
// ---------------------------------------------------------------------------
__global__ void zero_counts_kernel() {
    unsigned int i = blockIdx.x * blockDim.x + threadIdx.x;
    if (i < (unsigned int)(NSEG / 4))
        reinterpret_cast<uint4*>(g_counts)[i] = make_uint4(0u, 0u, 0u, 0u);
}

// ---------------------------------------------------------------------------
// K1b: per-point voxel id + histogram (480k small atomics, spread addresses)
// ---------------------------------------------------------------------------
__global__ void hist_kernel(const int* __restrict__ ind,
                            const int* __restrict__ bidx) {
    int i = blockIdx.x * blockDim.x + threadIdx.x;
    if (i >= NPTS) return;
    int2 xy = reinterpret_cast<const int2*>(ind)[i];
    int seg = bidx[i] * SEG_PER_B + xy.x * GYD + xy.y;
    g_seg[i] = seg;
    atomicAdd(&g_counts[seg], 1u);
}

// ---------------------------------------------------------------------------
// K2: per-1024-block exclusive scan of counts -> g_offs, block sums -> g_bsum
// ---------------------------------------------------------------------------
__global__ void scan_local_kernel() {
    __shared__ unsigned int sh[32];
    int i = blockIdx.x * 1024 + threadIdx.x;
    unsigned int v = g_counts[i];
    unsigned int incl = warp_incl_scan(v);
    int lane = threadIdx.x & 31, wid = threadIdx.x >> 5;
    if (lane == 31) sh[wid] = incl;
    __syncthreads();
    if (wid == 0) sh[lane] = warp_incl_scan(sh[lane]);
    __syncthreads();
    unsigned int base = wid ? sh[wid - 1] : 0u;
    g_offs[i] = base + incl - v;                 // exclusive within block
    if (threadIdx.x == 1023) g_bsum[blockIdx.x] = base + incl;  // block total
}

// ---------------------------------------------------------------------------
// K3: scan the 675 block sums (single block)
// ---------------------------------------------------------------------------
__global__ void scan_bsum_kernel() {
    __shared__ unsigned int sh[32];
    int t = threadIdx.x;
    unsigned int v = (t < SCAN_BLOCKS) ? g_bsum[t] : 0u;
    unsigned int incl = warp_incl_scan(v);
    int lane = t & 31, wid = t >> 5;
    if (lane == 31) sh[wid] = incl;
    __syncthreads();
    if (wid == 0) sh[lane] = warp_incl_scan(sh[lane]);
    __syncthreads();
    unsigned int base = wid ? sh[wid - 1] : 0u;
    if (t < SCAN_BLOCKS) g_bsum_sc[t] = base + incl - v;   // exclusive
}

// ---------------------------------------------------------------------------
// K5: place point ids in voxel-sorted order. After this,
//     end(v) = g_bsum_sc[v>>10] + g_offs[v],  start(v) = end(v) - g_counts[v]
// ---------------------------------------------------------------------------
__global__ void place_kernel() {
    int i = blockIdx.x * blockDim.x + threadIdx.x;
    if (i >= NPTS) return;
    int seg = g_seg[i];
    unsigned int slot = g_bsum_sc[seg >> 10] + atomicAdd(&g_offs[seg], 1u);
    g_order[slot] = (unsigned int)i;
}

// ---------------------------------------------------------------------------
// K6: fused gather + max-pool + Linear(64->32)+ReLU + transposed write.
// Block = 64 consecutive voxels, 256 threads.
// Pooling: 4 threads per voxel, 16 channels each (4x float4), sh_pool stride
// 80 floats -> conflict-free STS.128 staging.
// GEMV: warp owns 8 voxels, lane owns one output channel, W column in regs,
// warp-uniform broadcast LDS.128 reads. Output staged [32][65] then written
// 128B-coalesced.
// ---------------------------------------------------------------------------
constexpr int PSTRIDE = 80;

__global__ void __launch_bounds__(256, 2)
pool_gemv_kernel(const float* __restrict__ fea,
                 const float* __restrict__ W,
                 const float* __restrict__ bias,
                 float* __restrict__ out) {
    __shared__ float sh_pool[64 * PSTRIDE];    // 20 KB
    __shared__ float sh_out[COUT * 65];
    __shared__ unsigned int sh_cnt[64];
    __shared__ unsigned int sh_start[64];

    const int tid  = threadIdx.x;
    const int lane = tid & 31;
    const int wid  = tid >> 5;
    const int s0   = blockIdx.x * 64;

    if (tid < 64) {
        unsigned int c = g_counts[s0 + tid];
        unsigned int end = g_bsum_sc[(s0 + tid) >> 10] + g_offs[s0 + tid];
        sh_cnt[tid]   = c;
        sh_start[tid] = end - c;
    }

    // Lane-private W column + bias
    float wcol[64];
#pragma unroll
    for (int c = 0; c < 64; c++) wcol[c] = W[c * COUT + lane];
    const float bval = bias[lane];

    __syncthreads();

    // --- Pooling: thread -> (voxel s = tid>>2, channel quarter q = tid&3) ---
    {
        const int s  = tid >> 2;
        const int q  = tid & 3;          // channels 4q + 16m, m=0..3
        const unsigned int cnt = sh_cnt[s];
        if (cnt) {
            const unsigned int st = sh_start[s];
            float4 m0 = make_float4(-FLT_MAX, -FLT_MAX, -FLT_MAX, -FLT_MAX);
            float4 m1 = m0, m2 = m0, m3 = m0;
            for (unsigned int k = 0; k < cnt; ++k) {
                unsigned int p = g_order[st + k];
                const float4* f4 = reinterpret_cast<const float4*>(fea + (size_t)p * CIN);
                float4 a = f4[q + 0];
                float4 b = f4[q + 4];
                float4 cc = f4[q + 8];
                float4 d = f4[q + 12];
                m0.x = fmaxf(m0.x, a.x);  m0.y = fmaxf(m0.y, a.y);
                m0.z = fmaxf(m0.z, a.z);  m0.w = fmaxf(m0.w, a.w);
                m1.x = fmaxf(m1.x, b.x);  m1.y = fmaxf(m1.y, b.y);
                m1.z = fmaxf(m1.z, b.z);  m1.w = fmaxf(m1.w, b.w);
                m2.x = fmaxf(m2.x, cc.x); m2.y = fmaxf(m2.y, cc.y);
                m2.z = fmaxf(m2.z, cc.z); m2.w = fmaxf(m2.w, cc.w);
                m3.x = fmaxf(m3.x, d.x);  m3.y = fmaxf(m3.y, d.y);
                m3.z = fmaxf(m3.z, d.z);  m3.w = fmaxf(m3.w, d.w);
            }
            float4* dst = reinterpret_cast<float4*>(&sh_pool[s * PSTRIDE + q * 4]);
            dst[0] = m0;   // ch 4q+0..3
            dst[4] = m1;   // ch 4q+16..19
            dst[8] = m2;   // ch 4q+32..35
            dst[12] = m3;  // ch 4q+48..51
        }
    }
    __syncthreads();

    // --- GEMV: warp handles voxels wid*8..+7, lane owns output channel ---
#pragma unroll
    for (int j = 0; j < 8; j++) {
        int s = wid * 8 + j;
        float r = 0.0f;
        if (sh_cnt[s]) {
            float acc = bval;
            const float* pr = &sh_pool[s * PSTRIDE];
#pragma unroll
            for (int cs = 0; cs < 64; cs += 4) {
                float4 p = *reinterpret_cast<const float4*>(&pr[cs]);
                acc = fmaf(p.x, wcol[cs + 0], acc);
                acc = fmaf(p.y, wcol[cs + 1], acc);
                acc = fmaf(p.z, wcol[cs + 2], acc);
                acc = fmaf(p.w, wcol[cs + 3], acc);
            }
            r = fmaxf(acc, 0.0f);
        }
        sh_out[lane * 65 + s] = r;
    }
    __syncthreads();

    // --- Coalesced transposed write ---
    const int bb   = s0 / SEG_PER_B;
    const int rem0 = s0 - bb * SEG_PER_B;
    float* ob = out + (size_t)bb * COUT * SEG_PER_B + rem0;
#pragma unroll
    for (int it = 0; it < 8; it++) {
        int idx = tid + it * 256;
        int co = idx >> 6;
        int yy = idx & 63;
        ob[(size_t)co * SEG_PER_B + yy] = sh_out[co * 65 + yy];
    }
}

// ---------------------------------------------------------------------------
extern "C" void kernel_launch(void* const* d_in, const int* in_sizes, int n_in,
                              void* d_out, int out_size) {
    const float* pt_fea    = (const float*)d_in[0];
    const int*   pt_ind    = (const int*)d_in[1];
    const int*   batch_idx = (const int*)d_in[2];
    const float* W_comp    = (const float*)d_in[3];
    const float* b_comp    = (const float*)d_in[4];
    float* out = (float*)d_out;

    zero_counts_kernel<<<(NSEG / 4 + 255) / 256, 256>>>();
    hist_kernel<<<(NPTS + 255) / 256, 256>>>(pt_ind, batch_idx);
    scan_local_kernel<<<SCAN_BLOCKS, 1024>>>();
    scan_bsum_kernel<<<1, 1024>>>();
    place_kernel<<<(NPTS + 255) / 256, 256>>>();
    pool_gemv_kernel<<<NSEG / 64, 256>>>(pt_fea, W_comp, b_comp, out);
}